// round 4
// baseline (speedup 1.0000x reference)
#include <cuda_runtime.h>
#include <cstdint>

// WinCorr: corr[b,off,z,y,x] = (1/8) * sum_c x[b,c,z,y,x] * y[b,c,z+dz-1,y+dy-1,x+dx-1]
// x,y = (2,64,80,80,80) f32 ; out = (2,27,80,80,80) f32

#define B_  2
#define C_  64
#define D_  80
#define H_  80
#define W_  80

#define TZ  4
#define TY  8
#define TXB 16
#define TX  4
#define NTH 128

#define SMZ 6
#define SMY 10
#define SMXV 18          // valid columns
#define SMX 48           // stride mod 32 == 16 -> conflict-free LDS.128 wavefronts
#define NSTAGE (SMZ*SMY*SMXV)            // 1080
#define STAGES 4
#define BUFFLOATS (SMZ*SMY*SMX)          // 2880
#define BUFBYTES (BUFFLOATS*4)           // 11520 (x4 stages = 46080B static smem)

typedef unsigned long long u64;

__device__ __forceinline__ uint32_t smem_u32(const void* p) {
    return (uint32_t)__cvta_generic_to_shared(p);
}
__device__ __forceinline__ void cp_async4(uint32_t saddr, const void* gaddr, uint32_t srcsz) {
    asm volatile("cp.async.ca.shared.global [%0], [%1], 4, %2;\n"
                 :: "r"(saddr), "l"(gaddr), "r"(srcsz) : "memory");
}
__device__ __forceinline__ void cp_commit() {
    asm volatile("cp.async.commit_group;\n" ::: "memory");
}
template<int N> __device__ __forceinline__ void cp_wait() {
    asm volatile("cp.async.wait_group %0;\n" :: "n"(N) : "memory");
}
__device__ __forceinline__ void ffma2(u64& acc, u64 a, u64 b) {
    asm("fma.rn.f32x2 %0, %1, %2, %0;" : "+l"(acc) : "l"(a), "l"(b));
}
__device__ __forceinline__ u64 packf2(float lo, float hi) {
    u64 r; asm("mov.b64 %0, {%1, %2};" : "=l"(r) : "f"(lo), "f"(hi)); return r;
}
__device__ __forceinline__ float2 unpackf2(u64 v) {
    float2 r; asm("mov.b64 {%0, %1}, %2;" : "=f"(r.x), "=f"(r.y) : "l"(v)); return r;
}

__global__ void __launch_bounds__(NTH, 3)
wincorr_kernel(const float* __restrict__ x,
               const float* __restrict__ y,
               float* __restrict__ out)
{
    // ---- decode block -> (b, z0, y0, x0) ----
    int bid = blockIdx.x;
    int bx = bid % (W_ / TXB); bid /= (W_ / TXB);
    int by = bid % (H_ / TY);  bid /= (H_ / TY);
    int bz = bid % (D_ / TZ);  bid /= (D_ / TZ);
    int b  = bid;
    const int z0 = bz * TZ, y0 = by * TY, x0 = bx * TXB;

    const int tid = threadIdx.x;
    const int tx = tid & 3;
    const int ty = (tid >> 2) & 7;
    const int tz = tid >> 5;

    __shared__ __align__(16) float sm[STAGES][SMZ][SMY][SMX];

    const int plane = H_ * W_;       // 6400
    const int vol   = D_ * plane;    // 512000
    const uint32_t volbytes = (uint32_t)vol * 4u;

    const float* xb = x + (size_t)b * C_ * vol;
    const float* yb = y + (size_t)b * C_ * vol;
    const char*  ybc = (const char*)yb;

    // ---- precompute staging slots (channel-invariant); bit31 of goff = invalid ----
    uint32_t sadr[9];   // smem byte address (stage 0)
    uint32_t goff[9];   // byte offset into yb (clamped) | invalid<<31
#pragma unroll
    for (int k = 0; k < 9; k++) {
        int i = tid + k * NTH;
        int ii = (i < NSTAGE) ? i : 0;
        int lx = ii % SMXV;
        int t  = ii / SMXV;
        int ly = t % SMY;
        int lz = t / SMY;
        int gz = z0 - 1 + lz, gy = y0 - 1 + ly, gx = x0 - 1 + lx;
        bool inb = ((unsigned)gz < (unsigned)D_) &&
                   ((unsigned)gy < (unsigned)H_) &&
                   ((unsigned)gx < (unsigned)W_);
        int cz = min(max(gz, 0), D_ - 1);
        int cy = min(max(gy, 0), H_ - 1);
        int cx = min(max(gx, 0), W_ - 1);
        goff[k] = (uint32_t)((cz * plane + cy * W_ + cx) * 4) | (inb ? 0u : 0x80000000u);
        sadr[k] = smem_u32(&sm[0][lz][ly][lx]);
    }

    u64 acc01[27], acc23[27];
#pragma unroll
    for (int o = 0; o < 27; o++) { acc01[o] = 0ull; acc23[o] = 0ull; }

    const float* xp = xb + (size_t)(z0 + tz) * plane + (y0 + ty) * W_ + x0 + tx * TX;

    // ---- prologue: stage channels 0..2 (buffers 0..2), buffer 3 free ----
#pragma unroll
    for (int s = 0; s < STAGES - 1; s++) {
        const uint32_t cb = (uint32_t)s * volbytes;
        const uint32_t bo = (uint32_t)s * BUFBYTES;
#pragma unroll
        for (int k = 0; k < 9; k++) {
            if (tid + k * NTH < NSTAGE) {
                uint32_t g = goff[k];
                cp_async4(sadr[k] + bo, ybc + ((g & 0x7fffffffu) + cb),
                          (g >> 31) ? 0u : 4u);
            }
        }
        cp_commit();
    }

    float4 xv = __ldcs((const float4*)xp);

    for (int c = 0; c < C_; c++) {
        // stage c complete; stages c+1, c+2 may remain in flight
        cp_wait<2>();
        __syncthreads();   // stage c visible; all threads done reading buffer (c+3)%4 (iter c-1)

        // issue stage c+3 into buffer (c+3)%STAGES BEFORE the long compute block
        if (c + 3 < C_) {
            const uint32_t cb = (uint32_t)(c + 3) * volbytes;
            const uint32_t bo = (uint32_t)((c + 3) % STAGES) * BUFBYTES;
#pragma unroll
            for (int k = 0; k < 9; k++) {
                if (tid + k * NTH < NSTAGE) {
                    uint32_t g = goff[k];
                    cp_async4(sadr[k] + bo, ybc + ((g & 0x7fffffffu) + cb),
                              (g >> 31) ? 0u : 4u);
                }
            }
            cp_commit();
        }

        // prefetch x for c+1 (covered by the FFMA2 block below)
        float4 xnext;
        if (c + 1 < C_) xnext = __ldcs((const float4*)(xp + (size_t)(c + 1) * vol));

        const u64 xa01 = packf2(xv.x, xv.y);
        const u64 xa23 = packf2(xv.z, xv.w);
        const float (*smb)[SMY][SMX] = sm[c % STAGES];

#pragma unroll
        for (int dz = 0; dz < 3; dz++) {
#pragma unroll
            for (int dy = 0; dy < 3; dy++) {
                const float* row = &smb[tz + dz][ty + dy][tx * TX];
                // pairs straight from aligned vector loads (no repack for even pairs)
                const ulonglong2 q = *(const ulonglong2*)row;   // (l0,l1),(l2,l3)  LDS.128
                const u64 t64 = *(const u64*)(row + 4);         // (l4,l5)          LDS.64
                const float2 f01 = unpackf2(q.x);
                const float2 f23 = unpackf2(q.y);
                const float2 f45 = unpackf2(t64);
                const u64 p12 = packf2(f01.y, f23.x);
                const u64 p34 = packf2(f23.y, f45.x);
                const int ob = dz * 9 + dy * 3;
                ffma2(acc01[ob + 0], xa01, q.x);
                ffma2(acc23[ob + 0], xa23, q.y);
                ffma2(acc01[ob + 1], xa01, p12);
                ffma2(acc23[ob + 1], xa23, p34);
                ffma2(acc01[ob + 2], xa01, q.y);
                ffma2(acc23[ob + 2], xa23, t64);
            }
        }

        if (c + 1 < C_) xv = xnext;
    }

    // ---- epilogue: scale + streaming stores ----
    const float scale = 0.125f;
    const size_t sp = (size_t)(z0 + tz) * plane + (size_t)(y0 + ty) * W_ + (x0 + tx * TX);
    float* outb = out + (size_t)b * 27 * vol + sp;
#pragma unroll
    for (int off = 0; off < 27; off++) {
        float2 a  = unpackf2(acc01[off]);
        float2 bq = unpackf2(acc23[off]);
        float4 o;
        o.x = a.x * scale;
        o.y = a.y * scale;
        o.z = bq.x * scale;
        o.w = bq.y * scale;
        __stcs((float4*)(outb + (size_t)off * vol), o);
    }
}

extern "C" void kernel_launch(void* const* d_in, const int* in_sizes, int n_in,
                              void* d_out, int out_size)
{
    const float* x = (const float*)d_in[0];
    const float* y = (const float*)d_in[1];
    float* out = (float*)d_out;

    const int nblocks = B_ * (D_ / TZ) * (H_ / TY) * (W_ / TXB); // 2000
    wincorr_kernel<<<nblocks, NTH>>>(x, y, out);
}

// round 5
// speedup vs baseline: 1.2912x; 1.2912x over previous
#include <cuda_runtime.h>
#include <cstdint>

// WinCorr: corr[b,off,z,y,x] = (1/8) * sum_c x[b,c,z,y,x] * y[b,c,z+dz-1,y+dy-1,x+dx-1]
// x,y = (2,64,80,80,80) f32 ; out = (2,27,80,80,80) f32

#define B_  2
#define C_  64
#define D_  80
#define H_  80
#define W_  80

#define TZ  4
#define TY  8
#define TXB 8            // x extent per block
#define TX  2            // x outputs per thread
#define NTH 128

#define SMZ 6
#define SMY 10
#define SMXV 10          // valid columns (TXB + 2)
#define SMX 40           // row stride (floats): ty*40 mod 32 = 8*ty -> conflict-free LDS.64
#define NSTAGE (SMZ*SMY*SMXV)            // 600
#define NSLOT 5                          // ceil(600/128)
#define STAGES 3
#define BUFBYTES (SMZ*SMY*SMX*4)         // 9600 (x3 = 28800B)

typedef unsigned long long u64;

__device__ __forceinline__ uint32_t smem_u32(const void* p) {
    return (uint32_t)__cvta_generic_to_shared(p);
}
__device__ __forceinline__ void cp_async4(uint32_t saddr, const void* gaddr, uint32_t srcsz) {
    asm volatile("cp.async.ca.shared.global [%0], [%1], 4, %2;\n"
                 :: "r"(saddr), "l"(gaddr), "r"(srcsz) : "memory");
}
__device__ __forceinline__ void cp_commit() {
    asm volatile("cp.async.commit_group;\n" ::: "memory");
}
template<int N> __device__ __forceinline__ void cp_wait() {
    asm volatile("cp.async.wait_group %0;\n" :: "n"(N) : "memory");
}
__device__ __forceinline__ void ffma2(u64& acc, u64 a, u64 b) {
    asm("fma.rn.f32x2 %0, %1, %2, %0;" : "+l"(acc) : "l"(a), "l"(b));
}
__device__ __forceinline__ u64 packf2(float lo, float hi) {
    u64 r; asm("mov.b64 %0, {%1, %2};" : "=l"(r) : "f"(lo), "f"(hi)); return r;
}
__device__ __forceinline__ float2 unpackf2(u64 v) {
    float2 r; asm("mov.b64 {%0, %1}, %2;" : "=f"(r.x), "=f"(r.y) : "l"(v)); return r;
}

__global__ void __launch_bounds__(NTH, 5)
wincorr_kernel(const float* __restrict__ x,
               const float* __restrict__ y,
               float* __restrict__ out)
{
    // ---- decode block -> (b, z0, y0, x0) ----
    int bid = blockIdx.x;
    int bx = bid % (W_ / TXB); bid /= (W_ / TXB);   // 10
    int by = bid % (H_ / TY);  bid /= (H_ / TY);    // 10
    int bz = bid % (D_ / TZ);  bid /= (D_ / TZ);    // 20
    int b  = bid;
    const int z0 = bz * TZ, y0 = by * TY, x0 = bx * TXB;

    const int tid = threadIdx.x;
    const int tx = tid & 3;          // x-chunk (2 outputs each)
    const int ty = (tid >> 2) & 7;
    const int tz = tid >> 5;

    __shared__ __align__(16) float sm[STAGES][SMZ][SMY][SMX];

    const int plane = H_ * W_;       // 6400
    const int vol   = D_ * plane;    // 512000
    const uint32_t volbytes = (uint32_t)vol * 4u;

    const float* xb = x + (size_t)b * C_ * vol;
    const float* yb = y + (size_t)b * C_ * vol;
    const char*  ybc = (const char*)yb;

    // ---- precompute staging slots (channel-invariant); bit31 of goff = invalid ----
    uint32_t sadr[NSLOT];   // smem byte address (stage 0)
    uint32_t goff[NSLOT];   // byte offset into yb (clamped) | invalid<<31
#pragma unroll
    for (int k = 0; k < NSLOT; k++) {
        int i = tid + k * NTH;
        int ii = (i < NSTAGE) ? i : 0;
        int lx = ii % SMXV;
        int t  = ii / SMXV;
        int ly = t % SMY;
        int lz = t / SMY;
        int gz = z0 - 1 + lz, gy = y0 - 1 + ly, gx = x0 - 1 + lx;
        bool inb = ((unsigned)gz < (unsigned)D_) &&
                   ((unsigned)gy < (unsigned)H_) &&
                   ((unsigned)gx < (unsigned)W_);
        int cz = min(max(gz, 0), D_ - 1);
        int cy = min(max(gy, 0), H_ - 1);
        int cx = min(max(gx, 0), W_ - 1);
        goff[k] = (uint32_t)((cz * plane + cy * W_ + cx) * 4) | (inb ? 0u : 0x80000000u);
        sadr[k] = smem_u32(&sm[0][lz][ly][lx]);
    }

    u64 acc[27];
#pragma unroll
    for (int o = 0; o < 27; o++) acc[o] = 0ull;

    const float* xp = xb + (size_t)(z0 + tz) * plane + (y0 + ty) * W_ + x0 + tx * TX;

    // ---- prologue: stage channels 0 and 1 ----
#pragma unroll
    for (int s = 0; s < STAGES - 1; s++) {
        const uint32_t cb = (uint32_t)s * volbytes;
        const uint32_t bo = (uint32_t)s * BUFBYTES;
#pragma unroll
        for (int k = 0; k < NSLOT; k++) {
            if (tid + k * NTH < NSTAGE) {
                uint32_t g = goff[k];
                cp_async4(sadr[k] + bo, ybc + ((g & 0x7fffffffu) + cb),
                          (g >> 31) ? 0u : 4u);
            }
        }
        cp_commit();
    }

    float2 xv = *(const float2*)xp;

    for (int c = 0; c < C_; c++) {
        // stage c complete (stage c+1 may remain in flight)
        if (c == C_ - 1) cp_wait<0>(); else cp_wait<1>();
        __syncthreads();

        // issue stage c+2 into buffer (c+2)%3
        if (c + 2 < C_) {
            const uint32_t cb = (uint32_t)(c + 2) * volbytes;
            const uint32_t bo = (uint32_t)((c + 2) % STAGES) * BUFBYTES;
#pragma unroll
            for (int k = 0; k < NSLOT; k++) {
                if (tid + k * NTH < NSTAGE) {
                    uint32_t g = goff[k];
                    cp_async4(sadr[k] + bo, ybc + ((g & 0x7fffffffu) + cb),
                              (g >> 31) ? 0u : 4u);
                }
            }
            cp_commit();
        }

        // prefetch x for c+1 (covered by the FFMA2 block)
        float2 xnext;
        if (c + 1 < C_) xnext = *(const float2*)(xp + (size_t)(c + 1) * vol);

        const u64 xa = packf2(xv.x, xv.y);
        const float (*smb)[SMY][SMX] = sm[c % STAGES];

#pragma unroll
        for (int dz = 0; dz < 3; dz++) {
#pragma unroll
            for (int dy = 0; dy < 3; dy++) {
                const float* row = &smb[tz + dz][ty + dy][tx * TX];
                const u64 a  = *(const u64*)row;        // (c0,c1)  LDS.64, 8B aligned
                const u64 b2 = *(const u64*)(row + 2);  // (c2,c3)  LDS.64
                const float2 fa = unpackf2(a);
                const float2 fb = unpackf2(b2);
                const u64 p12 = packf2(fa.y, fb.x);     // (c1,c2)
                const int ob = dz * 9 + dy * 3;
                ffma2(acc[ob + 0], xa, a);
                ffma2(acc[ob + 1], xa, p12);
                ffma2(acc[ob + 2], xa, b2);
            }
        }

        if (c + 1 < C_) xv = xnext;
    }

    // ---- epilogue: scale + streaming stores ----
    const float scale = 0.125f;
    const size_t sp = (size_t)(z0 + tz) * plane + (size_t)(y0 + ty) * W_ + (x0 + tx * TX);
    float* outb = out + (size_t)b * 27 * vol + sp;
#pragma unroll
    for (int off = 0; off < 27; off++) {
        float2 a = unpackf2(acc[off]);
        float2 o;
        o.x = a.x * scale;
        o.y = a.y * scale;
        __stcs((float2*)(outb + (size_t)off * vol), o);
    }
}

extern "C" void kernel_launch(void* const* d_in, const int* in_sizes, int n_in,
                              void* d_out, int out_size)
{
    const float* x = (const float*)d_in[0];
    const float* y = (const float*)d_in[1];
    float* out = (float*)d_out;

    const int nblocks = B_ * (D_ / TZ) * (H_ / TY) * (W_ / TXB); // 2*20*10*10 = 4000
    wincorr_kernel<<<nblocks, NTH>>>(x, y, out);
}